// round 6
// baseline (speedup 1.0000x reference)
#include <cuda_runtime.h>
#include <math.h>
#include <stdint.h>

// ---------------------------------------------------------------------------
// Shapes (fixed)
// ---------------------------------------------------------------------------
#define Hd 1024
#define Fd 4096
#define Ed 8
#define Td 512
#define OUT_TOK 2048

// ---------------------------------------------------------------------------
// Static device scratch (allocation-free per harness rules)
// ---------------------------------------------------------------------------
__device__ float g_buf [Ed * Td * Hd];                  // dispatched acts (tf32-rounded)
__device__ float g_hmid[(size_t)Ed * Td * Fd];          // GEMM1+GELU out (tf32-rounded)
__device__ float g_obuf[Ed * Td * Hd];                  // GEMM2 out (fp32)
__device__ int   g_order[Td][Ed];
__device__ float g_score[Td][Ed];

// ---------------------------------------------------------------------------
// Helpers
// ---------------------------------------------------------------------------
__device__ __forceinline__ uint32_t smem_u32(const void* p) {
    uint32_t a;
    asm("{ .reg .u64 t; cvta.to.shared.u64 t, %1; cvt.u32.u64 %0, t; }" : "=r"(a) : "l"(p));
    return a;
}
__device__ __forceinline__ float tf32r(float x) {
    uint32_t u;
    asm("cvt.rna.tf32.f32 %0, %1;" : "=r"(u) : "f"(x));
    return __uint_as_float(u);
}
__device__ __forceinline__ void cp_async16(uint32_t saddr, const void* gaddr) {
    asm volatile("cp.async.cg.shared.global [%0], [%1], 16;" :: "r"(saddr), "l"(gaddr));
}
__device__ __forceinline__ void cp_commit() {
    asm volatile("cp.async.commit_group;" ::: "memory");
}
__device__ __forceinline__ void cp_wait2() {
    asm volatile("cp.async.wait_group 2;" ::: "memory");
}
__device__ __forceinline__ void mma_tf32(float c[4], uint32_t a0, uint32_t a1,
                                         uint32_t a2, uint32_t a3,
                                         uint32_t b0, uint32_t b1) {
    asm volatile(
        "mma.sync.aligned.m16n8k8.row.col.f32.tf32.tf32.f32 "
        "{%0,%1,%2,%3}, {%4,%5,%6,%7}, {%8,%9}, {%0,%1,%2,%3};"
        : "+f"(c[0]), "+f"(c[1]), "+f"(c[2]), "+f"(c[3])
        : "r"(a0), "r"(a1), "r"(a2), "r"(a3), "r"(b0), "r"(b1));
}
__device__ __forceinline__ float gelu_exact(float v) {
    return 0.5f * v * (1.0f + erff(v * 0.70710678118654752f));
}

// ---------------------------------------------------------------------------
// Gating
// ---------------------------------------------------------------------------
__global__ void gate_kernel(const float* __restrict__ x,
                            const float* __restrict__ Wg,
                            const float* __restrict__ bg) {
    int warp = threadIdx.x >> 5;
    int lane = threadIdx.x & 31;
    int t = blockIdx.x * 8 + warp;
    if (t >= Td) return;

    const float* xr = x + (size_t)t * Hd;
    float acc[Ed];
#pragma unroll
    for (int e = 0; e < Ed; e++) acc[e] = 0.f;
    for (int h = lane; h < Hd; h += 32) {
        float xv = xr[h];
        const float* wr = Wg + (size_t)h * Ed;
#pragma unroll
        for (int e = 0; e < Ed; e++) acc[e] += xv * wr[e];
    }
#pragma unroll
    for (int e = 0; e < Ed; e++) {
#pragma unroll
        for (int o = 16; o > 0; o >>= 1)
            acc[e] += __shfl_xor_sync(0xffffffffu, acc[e], o);
    }
    if (lane == 0) {
        float l[Ed], p[Ed];
        float mx = -1e30f;
#pragma unroll
        for (int e = 0; e < Ed; e++) { l[e] = acc[e] + bg[e]; mx = fmaxf(mx, l[e]); }
        float s = 0.f;
#pragma unroll
        for (int e = 0; e < Ed; e++) { p[e] = expf(l[e] - mx); s += p[e]; }
#pragma unroll
        for (int e = 0; e < Ed; e++) p[e] /= s;
        float sum = 0.f;
#pragma unroll
        for (int e = 0; e < Ed; e++) sum += p[e];
        float inv = 1.0f / (sum + 1e-9f);
        bool used[Ed];
#pragma unroll
        for (int e = 0; e < Ed; e++) used[e] = false;
        for (int r = 0; r < Ed; r++) {
            int best = -1; float bv = -1e30f;
            for (int e = 0; e < Ed; e++)
                if (!used[e] && p[e] > bv) { bv = p[e]; best = e; }
            used[best] = true;
            g_order[t][r] = best;
            g_score[t][r] = bv * inv;
        }
    }
}

// ---------------------------------------------------------------------------
// Dispatch (tf32-rounds the MMA A operand)
// ---------------------------------------------------------------------------
__global__ void dispatch_kernel(const float* __restrict__ x) {
    int t = blockIdx.x;
    int r = blockIdx.y;
    int e = g_order[t][r];
    float sc = g_score[t][r];
    int src = 4 * t + (r >> 1);
    const float4* xs = (const float4*)(x + (size_t)src * Hd);
    float4* dst = (float4*)(g_buf + ((size_t)e * Td + t) * Hd);
    float4 v = xs[threadIdx.x];
    v.x = tf32r(v.x * sc); v.y = tf32r(v.y * sc);
    v.z = tf32r(v.z * sc); v.w = tf32r(v.w * sc);
    dst[threadIdx.x] = v;
}

// ---------------------------------------------------------------------------
// tf32 mma.sync GEMM: C[e][Td x Ndim] = A[e][Td x Kdim] @ B[e][Kdim x Ndim]
//  - B consumed in ORIGINAL [K][N] layout; transposed to K-major SMEM during
//    staging. Deep pipeline: B data held in regs one extra iteration
//    (LDG at iter i -> STS at iter i+1 top -> read at iter i+3... stage i+3).
//  - A: 4-stage cp.async (wait_group 2) -> 3 iterations of slack.
//  - BM=128 BN=128 BK=16, warp grid 2x4, 64x32 per warp.
// ---------------------------------------------------------------------------
#define LDSSTR 20
#define TILE_WORDS (128 * LDSSTR)          // per-operand per-stage words
// A: 4 stages, B: 3 stages
#define GEMM_SMEM_BYTES ((4 + 3) * TILE_WORDS * 4)   // 71680

template <int Kdim, int Ndim, bool DoGelu>
__global__ __launch_bounds__(256, 2)
void gemm_mma(const float* __restrict__ A_, const float* __restrict__ B_,
              const float* __restrict__ bias_, float* __restrict__ C_) {
    constexpr int BK = 16;
    constexpr int NK = Kdim / BK;

    extern __shared__ float smem[];
    float* AsBase = smem;                       // [4][128][20]
    float* BsBase = smem + 4 * TILE_WORDS;      // [3][128 n][20 k]

    const int e  = blockIdx.z;
    const int m0 = blockIdx.y * 128;
    const int n0 = blockIdx.x * 128;
    const int tid = threadIdx.x;

    const float* Ag = A_ + (size_t)e * Td * Kdim;
    const float* BgE = B_ + (size_t)e * Kdim * Ndim;   // [K][N] row-major

    // ---- A loader (cp.async, K-major already) ----
    const int lrow = tid >> 1;                  // 0..127
    const int lcol = (tid & 1) * 8;             // 0 or 8
    const uint32_t sA0 = smem_u32(AsBase) + (uint32_t)(lrow * LDSSTR + lcol) * 4;
    const float* gA0 = Ag + (size_t)(m0 + lrow) * Kdim + lcol;

    auto cpA = [&](int i) {
        uint32_t sa = sA0 + (uint32_t)((i & 3) * TILE_WORDS) * 4;
        const float* ga = gA0 + i * BK;
        cp_async16(sa, ga);
        cp_async16(sa + 16, ga + 4);
        cp_commit();
    };

    // ---- B loader: thread covers column n_b, k-rows {4*kq..} and {4*kq+8..} ----
    const int n_b = tid & 127;
    const int kq  = tid >> 7;                   // 0..1
    const float* gB0 = BgE + (size_t)(kq * 4) * Ndim + n0 + n_b;
    float br[8];

    auto ldgB = [&](int i) {
        const float* p = gB0 + (size_t)(i * BK) * Ndim;
#pragma unroll
        for (int ii = 0; ii < 4; ii++) br[ii] = tf32r(p[(size_t)ii * Ndim]);
        const float* p2 = p + (size_t)8 * Ndim;
#pragma unroll
        for (int ii = 0; ii < 4; ii++) br[4 + ii] = tf32r(p2[(size_t)ii * Ndim]);
    };
    auto stsB = [&](int i) {
        float* bs = BsBase + (i % 3) * TILE_WORDS + n_b * LDSSTR + kq * 4;
        *(float4*)(bs)     = *(const float4*)&br[0];
        *(float4*)(bs + 8) = *(const float4*)&br[4];
    };

    // ---- warp/fragment mapping ----
    const int wid = tid >> 5;
    const int lane = tid & 31;
    const int wm = wid >> 2;                    // 0..1
    const int wn = wid & 3;                     // 0..3
    const int grp = lane >> 2;                  // 0..7
    const int tg  = lane & 3;                   // 0..3

    float c[4][4][4];
#pragma unroll
    for (int mt = 0; mt < 4; mt++)
#pragma unroll
        for (int nt = 0; nt < 4; nt++)
#pragma unroll
            for (int q = 0; q < 4; q++) c[mt][nt][q] = 0.f;

    // prologue: B stages 0,1 stored; B chunk 2 held in regs; A stages 0..2
    ldgB(0); stsB(0);
    ldgB(1); stsB(1);
    cpA(0);  cpA(1);  cpA(2);
    ldgB(2);

    for (int i = 0; i < NK; i++) {
        cp_wait2();
        __syncthreads();
        // STS the B chunk loaded last iteration (stage i+2); the barrier above
        // guarantees stage (i+2)%3 == (i-1)%3 is no longer being read.
        if (i + 2 < NK) stsB(i + 2);
        if (i + 3 < NK) { ldgB(i + 3); cpA(i + 3); }
        else cp_commit();            // keep wait_group window advancing

        const uint32_t* as = (const uint32_t*)(AsBase + (i & 3) * TILE_WORDS);
        const uint32_t* bs = (const uint32_t*)(BsBase + (i % 3) * TILE_WORDS);

#pragma unroll
        for (int kk = 0; kk < 2; kk++) {
            const int kb = kk * 8 + tg;
            uint32_t a[4][4], b[4][2];
#pragma unroll
            for (int mt = 0; mt < 4; mt++) {
                int r = wm * 64 + mt * 16 + grp;
                a[mt][0] = as[r * LDSSTR + kb];
                a[mt][1] = as[(r + 8) * LDSSTR + kb];
                a[mt][2] = as[r * LDSSTR + kb + 4];
                a[mt][3] = as[(r + 8) * LDSSTR + kb + 4];
            }
#pragma unroll
            for (int nt = 0; nt < 4; nt++) {
                int cn = wn * 32 + nt * 8 + grp;
                b[nt][0] = bs[cn * LDSSTR + kb];
                b[nt][1] = bs[cn * LDSSTR + kb + 4];
            }
#pragma unroll
            for (int mt = 0; mt < 4; mt++)
#pragma unroll
                for (int nt = 0; nt < 4; nt++)
                    mma_tf32(c[mt][nt], a[mt][0], a[mt][1], a[mt][2], a[mt][3],
                             b[nt][0], b[nt][1]);
        }
    }

    // Epilogue: bias (+GELU +tf32 round), float2 stores
    const float* bias = bias_ + (size_t)e * Ndim + n0;
    float* C = C_ + (size_t)e * Td * Ndim;
#pragma unroll
    for (int mt = 0; mt < 4; mt++) {
        int r0 = m0 + wm * 64 + mt * 16 + grp;
#pragma unroll
        for (int nt = 0; nt < 4; nt++) {
            int col = wn * 32 + nt * 8 + tg * 2;
            float bx = bias[col], by = bias[col + 1];
            float2 v0, v1;
            v0.x = c[mt][nt][0] + bx;  v0.y = c[mt][nt][1] + by;
            v1.x = c[mt][nt][2] + bx;  v1.y = c[mt][nt][3] + by;
            if (DoGelu) {
                v0.x = tf32r(gelu_exact(v0.x)); v0.y = tf32r(gelu_exact(v0.y));
                v1.x = tf32r(gelu_exact(v1.x)); v1.y = tf32r(gelu_exact(v1.y));
            }
            *(float2*)(C + (size_t)r0 * Ndim + n0 + col) = v0;
            *(float2*)(C + (size_t)(r0 + 8) * Ndim + n0 + col) = v1;
        }
    }
}

// ---------------------------------------------------------------------------
// Combine
// ---------------------------------------------------------------------------
__global__ void combine_kernel(float* __restrict__ out) {
    int m = blockIdx.x;
    int t = m >> 2;
    int q = m & 3;
    int e1 = g_order[t][2 * q];
    int e2 = g_order[t][2 * q + 1];
    const float4* o1 = (const float4*)(g_obuf + ((size_t)e1 * Td + t) * Hd);
    const float4* o2 = (const float4*)(g_obuf + ((size_t)e2 * Td + t) * Hd);
    float4* dst = (float4*)(out + (size_t)m * Hd);
    float4 a = o1[threadIdx.x];
    float4 b = o2[threadIdx.x];
    float4 v; v.x = a.x + b.x; v.y = a.y + b.y; v.z = a.z + b.z; v.w = a.w + b.w;
    dst[threadIdx.x] = v;
}

// ---------------------------------------------------------------------------
extern "C" void kernel_launch(void* const* d_in, const int* in_sizes, int n_in,
                              void* d_out, int out_size) {
    (void)in_sizes; (void)n_in;
    const float* x  = (const float*)d_in[0];
    const float* Wg = (const float*)d_in[1];
    const float* bg = (const float*)d_in[2];
    const float* W1 = (const float*)d_in[3];
    const float* b1 = (const float*)d_in[4];
    const float* W2 = (const float*)d_in[5];
    const float* b2 = (const float*)d_in[6];
    float* out = (float*)d_out;

    float *buf, *hmid, *obuf;
    cudaGetSymbolAddress((void**)&buf,  g_buf);
    cudaGetSymbolAddress((void**)&hmid, g_hmid);
    cudaGetSymbolAddress((void**)&obuf, g_obuf);

    cudaFuncSetAttribute(gemm_mma<Hd, Fd, true>,
                         cudaFuncAttributeMaxDynamicSharedMemorySize, GEMM_SMEM_BYTES);
    cudaFuncSetAttribute(gemm_mma<Fd, Hd, false>,
                         cudaFuncAttributeMaxDynamicSharedMemorySize, GEMM_SMEM_BYTES);

    // Output tail (batches 1-3 + aux-loss scalar, all exactly zero)
    size_t nz = (size_t)OUT_TOK * Hd;
    cudaMemsetAsync(out + nz, 0, ((size_t)out_size - nz) * sizeof(float), 0);

    gate_kernel<<<Td / 8, 256>>>(x, Wg, bg);
    dispatch_kernel<<<dim3(Td, Ed), 256>>>(x);

    // GEMM1 + GELU: per expert (512 x 1024) @ (1024 x 4096), B in native layout
    gemm_mma<Hd, Fd, true><<<dim3(Fd / 128, Td / 128, Ed), 256, GEMM_SMEM_BYTES>>>(buf, W1, b1, hmid);
    // GEMM2: per expert (512 x 4096) @ (4096 x 1024), B in native layout
    gemm_mma<Fd, Hd, false><<<dim3(Hd / 128, Td / 128, Ed), 256, GEMM_SMEM_BYTES>>>(hmid, W2, b2, obuf);

    combine_kernel<<<OUT_TOK, 256>>>(out);
}